// round 15
// baseline (speedup 1.0000x reference)
#include <cuda_runtime.h>
#include <cstddef>
#include <cstdint>
#include <math.h>

#define MM      16384
#define DD      1280
#define INNER   5120
#define NN1     10240
#define RR      32
#define G1      (DD / 64)
#define G2      (INNER / 64)

// ---------------------------------------------------------------------------
// Scratch
// ---------------------------------------------------------------------------
__device__ int8_t g_qx [(size_t)MM * DD];
__device__ int8_t g_qw1[(size_t)NN1 * DD];
__device__ int8_t g_qw2[(size_t)DD * INNER];
__device__ int8_t g_qg [(size_t)MM * INNER];
__device__ float  g_sxT [(size_t)G1 * MM];
__device__ float  g_sw1T[(size_t)G1 * NN1];
__device__ float  g_sw2T[(size_t)G2 * DD];
__device__ float  g_sgT [(size_t)G2 * MM];
__device__ float  g_H [(size_t)MM * NN1];
__device__ float  g_G [(size_t)MM * INNER];
__device__ float  g_T1[(size_t)MM * RR];
__device__ float  g_T2[(size_t)MM * RR];

__device__ __forceinline__ float warp_max_f(float v) {
#pragma unroll
    for (int o = 16; o > 0; o >>= 1)
        v = fmaxf(v, __shfl_xor_sync(0xffffffffu, v, o));
    return v;
}
__device__ __forceinline__ float div_rcp(float x, float y) {
    return __fmul_rn(x, __frcp_rn(y));
}

// ---------------------------------------------------------------------------
// fake_quant (rcp arithmetic) -> int8 codes + transposed per-group scales
// ---------------------------------------------------------------------------
__global__ void quant_groups_i8(const float* __restrict__ src,
                                int8_t* __restrict__ q, float* __restrict__ sT,
                                int gpr, int K, int rows, int total_groups)
{
    int wid = (blockIdx.x * blockDim.x + threadIdx.x) >> 5;
    if (wid >= total_groups) return;
    int lane = threadIdx.x & 31;
    int row  = wid / gpr;
    int g    = wid - row * gpr;
    int col0 = g * 64;
    const float* s = src + (size_t)row * K + col0;
    float v0 = s[lane], v1 = s[lane + 32];
    float m = warp_max_f(fmaxf(fabsf(v0), fabsf(v1)));
    float scale = fmaxf(div_rcp(m, 7.0f), 1e-8f);
    float rs = __frcp_rn(scale);
    float q0 = fminf(fmaxf(rintf(__fmul_rn(v0, rs)), -8.0f), 7.0f);
    float q1 = fminf(fmaxf(rintf(__fmul_rn(v1, rs)), -8.0f), 7.0f);
    int8_t* d = q + (size_t)row * K + col0;
    d[lane]      = (int8_t)q0;
    d[lane + 32] = (int8_t)q1;
    if (lane == 0) sT[(size_t)g * rows + row] = scale;
}

// ---------------------------------------------------------------------------
// GEGLU (erff, rcp) + requant of g -> int8 + scales; raw g kept for t2.
// ---------------------------------------------------------------------------
__global__ void gelu_quant_i8(const float* __restrict__ H, float* __restrict__ G,
                              int8_t* __restrict__ qg, float* __restrict__ sgT,
                              int total_groups)
{
    int wid = (blockIdx.x * blockDim.x + threadIdx.x) >> 5;
    if (wid >= total_groups) return;
    int lane = threadIdx.x & 31;
    int row  = wid / G2;
    int g    = wid - row * G2;
    int col0 = g * 64;
    const float* h = H + (size_t)row * NN1 + col0;

    const float SQRT2 = 1.41421356237309504880f;
    float a0 = h[lane],      x0 = h[lane + INNER];
    float a1 = h[lane + 32], x1 = h[lane + 32 + INNER];
    float e0 = erff(div_rcp(x0, SQRT2));
    float e1 = erff(div_rcp(x1, SQRT2));
    float g0 = __fmul_rn(a0, __fmul_rn(__fmul_rn(0.5f, x0), __fadd_rn(e0, 1.0f)));
    float g1 = __fmul_rn(a1, __fmul_rn(__fmul_rn(0.5f, x1), __fadd_rn(e1, 1.0f)));

    float* gp = G + (size_t)row * INNER + col0;
    gp[lane]      = g0;
    gp[lane + 32] = g1;

    float m = warp_max_f(fmaxf(fabsf(g0), fabsf(g1)));
    float scale = fmaxf(div_rcp(m, 7.0f), 1e-8f);
    float rs = __frcp_rn(scale);
    float q0 = fminf(fmaxf(rintf(__fmul_rn(g0, rs)), -8.0f), 7.0f);
    float q1 = fminf(fmaxf(rintf(__fmul_rn(g1, rs)), -8.0f), 7.0f);
    int8_t* d = qg + (size_t)row * INNER + col0;
    d[lane]      = (int8_t)q0;
    d[lane + 32] = (int8_t)q1;
    if (lane == 0) sgT[(size_t)g * MM + row] = scale;
}

// ---------------------------------------------------------------------------
// Pipelined group-scaled int8 tensor-core GEMM (NT) with FUSED LoRA epilogue:
//   C[m,n] = lora(m,n) + sum_g sA[g][m]*sB[g][n]*Dg(m,n)
//   lora(m,n) = ascending-k FMA chain over Tlo[m,0..31]*Ulo[n,0..31]
// (bit-identical to the old separate K=32 gemm_nt + single fadd).
// ---------------------------------------------------------------------------
#define STAGES  3
#define ASTRIDE 144
#define TILEB   (128 * ASTRIDE)
#define LSTRIDE 36
#define MAGIC_I 0x4B400000
#define MAGIC_F 12582912.0f

#define CP16(d, s) asm volatile("cp.async.cg.shared.global [%0], [%1], 16;\n" :: "r"(d), "l"(s))
#define CP4(d, s)  asm volatile("cp.async.ca.shared.global [%0], [%1], 4;\n"  :: "r"(d), "l"(s))
#define CP_COMMIT  asm volatile("cp.async.commit_group;\n")

__global__ void __launch_bounds__(256, 1)
imma_gemm(const int8_t* __restrict__ qA, const float* __restrict__ sAT,
          const int8_t* __restrict__ qB, const float* __restrict__ sBT,
          const float* __restrict__ Tlo, const float* __restrict__ Ulo,
          float* __restrict__ C, int M, int N, int K)
{
    extern __shared__ char dsm[];
    int8_t* smA = (int8_t*)dsm;
    int8_t* smB = (int8_t*)(dsm + STAGES * TILEB);
    float*  ssA = (float*)(dsm + 2 * STAGES * TILEB);
    float*  ssB = ssA + STAGES * 256;
    float*  Ts  = ssB + STAGES * 256;         // 128 x LSTRIDE
    float*  Us  = Ts + 128 * LSTRIDE;         // 128 x LSTRIDE

    const int tid  = threadIdx.x;
    const int lane = tid & 31;
    const int wid  = tid >> 5;
    const int wm   = (wid >> 2) * 64;
    const int wn   = (wid & 3) * 32;
    const int bm   = blockIdx.y * 128;
    const int bn   = blockIdx.x * 128;
    const int nC   = K >> 7;

    const uint32_t smA_u = (uint32_t)__cvta_generic_to_shared(smA);
    const uint32_t smB_u = (uint32_t)__cvta_generic_to_shared(smB);
    const uint32_t ssA_u = (uint32_t)__cvta_generic_to_shared(ssA);
    const uint32_t ssB_u = (uint32_t)__cvta_generic_to_shared(ssB);

    const int lr0  = tid >> 3;
    const int lseg = tid & 7;

    float facc[16][4];
#pragma unroll
    for (int i = 0; i < 16; ++i)
#pragma unroll
        for (int j = 0; j < 4; ++j) facc[i][j] = 0.0f;

    const int a_r  = (lane & 7) + ((lane & 8) ? 8 : 0);
    const int a_cb = (lane & 16) ? 16 : 0;
    const int b_r  = lane & 7;
    const int b_cb = (lane & 8) ? 16 : 0;

    const int sg2 = tid >> 7;
    const int sr  = tid & 127;

    auto load_stage = [&](int chunk, int slot) {
        const int8_t* gA = qA + (size_t)bm * K + (size_t)chunk * 128;
        const int8_t* gB = qB + (size_t)bn * K + (size_t)chunk * 128;
        uint32_t aB = smA_u + slot * TILEB;
        uint32_t bB = smB_u + slot * TILEB;
#pragma unroll
        for (int t = 0; t < 4; ++t) {
            int r = lr0 + t * 32;
            CP16(aB + r * ASTRIDE + lseg * 16, gA + (size_t)r * K + lseg * 16);
        }
#pragma unroll
        for (int t = 0; t < 4; ++t) {
            int r = lr0 + t * 32;
            CP16(bB + r * ASTRIDE + lseg * 16, gB + (size_t)r * K + lseg * 16);
        }
        CP4(ssA_u + (slot * 256 + sg2 * 128 + sr) * 4,
            sAT + (size_t)(chunk * 2 + sg2) * M + bm + sr);
        CP4(ssB_u + (slot * 256 + sg2 * 128 + sr) * 4,
            sBT + (size_t)(chunk * 2 + sg2) * N + bn + sr);
        CP_COMMIT;
    };

    // load LoRA tiles (covered by the first __syncthreads in the main loop)
    {
        const float* Tg = Tlo + (size_t)bm * RR;
        const float* Ug = Ulo + (size_t)bn * RR;
#pragma unroll
        for (int i = tid; i < 128 * 8; i += 256) {
            int r = i >> 3, c4 = (i & 7) * 4;
            float4 v = *(const float4*)(Tg + (size_t)r * RR + c4);
            *(float4*)(Ts + r * LSTRIDE + c4) = v;
            float4 u = *(const float4*)(Ug + (size_t)r * RR + c4);
            *(float4*)(Us + r * LSTRIDE + c4) = u;
        }
    }

#pragma unroll
    for (int s = 0; s < STAGES - 1; ++s)
        load_stage(s, s);

    const int r0 = lane >> 2;
    const int c0 = (lane & 3) * 2;

    for (int c = 0; c < nC; ++c) {
        if (c + STAGES - 1 < nC)
            load_stage(c + STAGES - 1, (c + STAGES - 1) % STAGES);
        asm volatile("cp.async.wait_group %0;\n" :: "n"(STAGES - 1));
        __syncthreads();

        const int slot = c % STAGES;
        const uint32_t aB = smA_u + slot * TILEB;
        const uint32_t bB = smB_u + slot * TILEB;
        const float* sAv = ssA + slot * 256;
        const float* sBv = ssB + slot * 256;

#pragma unroll
        for (int g2 = 0; g2 < 2; ++g2) {
            uint32_t af[2][4][4], bf[2][4][2];
#pragma unroll
            for (int kk = 0; kk < 2; ++kk) {
#pragma unroll
                for (int mi = 0; mi < 4; ++mi) {
                    uint32_t addr = aB + (wm + mi * 16 + a_r) * ASTRIDE
                                  + g2 * 64 + kk * 32 + a_cb;
                    asm volatile(
                        "ldmatrix.sync.aligned.m8n8.x4.shared.b16 {%0,%1,%2,%3}, [%4];"
                        : "=r"(af[kk][mi][0]), "=r"(af[kk][mi][1]),
                          "=r"(af[kk][mi][2]), "=r"(af[kk][mi][3])
                        : "r"(addr));
                }
#pragma unroll
                for (int ni = 0; ni < 4; ++ni) {
                    uint32_t addr = bB + (wn + ni * 8 + b_r) * ASTRIDE
                                  + g2 * 64 + kk * 32 + b_cb;
                    asm volatile(
                        "ldmatrix.sync.aligned.m8n8.x2.shared.b16 {%0,%1}, [%2];"
                        : "=r"(bf[kk][ni][0]), "=r"(bf[kk][ni][1])
                        : "r"(addr));
                }
            }
            const float* sag = sAv + g2 * 128;
            const float* sbg = sBv + g2 * 128;
#pragma unroll
            for (int mi = 0; mi < 4; ++mi) {
                float sa0 = sag[wm + mi * 16 + r0];
                float sa1 = sag[wm + mi * 16 + r0 + 8];
#pragma unroll
                for (int ni = 0; ni < 4; ++ni) {
                    int cacc[4] = {MAGIC_I, MAGIC_I, MAGIC_I, MAGIC_I};
#pragma unroll
                    for (int kk = 0; kk < 2; ++kk)
                        asm volatile(
                            "mma.sync.aligned.m16n8k32.row.col.s32.s8.s8.s32 "
                            "{%0,%1,%2,%3}, {%4,%5,%6,%7}, {%8,%9}, {%0,%1,%2,%3};"
                            : "+r"(cacc[0]), "+r"(cacc[1]), "+r"(cacc[2]), "+r"(cacc[3])
                            : "r"(af[kk][mi][0]), "r"(af[kk][mi][1]),
                              "r"(af[kk][mi][2]), "r"(af[kk][mi][3]),
                              "r"(bf[kk][ni][0]), "r"(bf[kk][ni][1]));
                    float sb0 = sbg[wn + ni * 8 + c0];
                    float sb1 = sbg[wn + ni * 8 + c0 + 1];
                    int idx = mi * 4 + ni;
                    float d0 = __fadd_rn(__int_as_float(cacc[0]), -MAGIC_F);
                    float d1 = __fadd_rn(__int_as_float(cacc[1]), -MAGIC_F);
                    float d2 = __fadd_rn(__int_as_float(cacc[2]), -MAGIC_F);
                    float d3 = __fadd_rn(__int_as_float(cacc[3]), -MAGIC_F);
                    facc[idx][0] = __fmaf_rn(__fmul_rn(sa0, sb0), d0, facc[idx][0]);
                    facc[idx][1] = __fmaf_rn(__fmul_rn(sa0, sb1), d1, facc[idx][1]);
                    facc[idx][2] = __fmaf_rn(__fmul_rn(sa1, sb0), d2, facc[idx][2]);
                    facc[idx][3] = __fmaf_rn(__fmul_rn(sa1, sb1), d3, facc[idx][3]);
                }
            }
        }
        __syncthreads();
    }

    // ---- fused LoRA epilogue: ascending-k FMA chain + single fadd ----
#pragma unroll
    for (int mi = 0; mi < 4; ++mi) {
        const float* t0 = Ts + (wm + mi * 16 + r0) * LSTRIDE;
        const float* t1 = t0 + 8 * LSTRIDE;
#pragma unroll
        for (int ni = 0; ni < 4; ++ni) {
            const float* u0 = Us + (wn + ni * 8 + c0) * LSTRIDE;
            const float* u1 = u0 + LSTRIDE;
            float l00 = 0.f, l01 = 0.f, l10 = 0.f, l11 = 0.f;
#pragma unroll
            for (int k = 0; k < RR; ++k) {
                float tv0 = t0[k], tv1 = t1[k];
                float uv0 = u0[k], uv1 = u1[k];
                l00 = __fmaf_rn(tv0, uv0, l00);
                l01 = __fmaf_rn(tv0, uv1, l01);
                l10 = __fmaf_rn(tv1, uv0, l10);
                l11 = __fmaf_rn(tv1, uv1, l11);
            }
            int idx = mi * 4 + ni;
            int row = bm + wm + mi * 16 + r0;
            int col = bn + wn + ni * 8 + c0;
            *(float2*)&C[(size_t)row * N + col] =
                make_float2(__fadd_rn(l00, facc[idx][0]),
                            __fadd_rn(l01, facc[idx][1]));
            *(float2*)&C[(size_t)(row + 8) * N + col] =
                make_float2(__fadd_rn(l10, facc[idx][2]),
                            __fadd_rn(l11, facc[idx][3]));
        }
    }
}

// ---------------------------------------------------------------------------
// Skinny tall GEMM: C[M,32] = A[M,K] @ B[32,K]^T (ascending-k FMA chain).
// ---------------------------------------------------------------------------
#define TBM 64
#define TBK 32

__global__ void __launch_bounds__(256, 2)
gemm_tall(const float* __restrict__ A, int lda,
          const float* __restrict__ B,
          float* __restrict__ C, int K)
{
    __shared__ float As[TBK][TBM + 4];
    __shared__ float Bs[TBK][RR];

    const int tid  = threadIdx.x;
    const int lane = tid & 31;
    const int wrow = (tid >> 5) * 8;
    const int bm   = blockIdx.x * TBM;

    float acc[8];
#pragma unroll
    for (int i = 0; i < 8; ++i) acc[i] = 0.0f;

    const int ar = tid >> 2;
    const int ac = (tid & 3) * 8;
    const int br = tid >> 3;
    const int bc = (tid & 7) * 4;

    for (int kt = 0; kt < K / TBK; ++kt) {
        float4 va0 = *(const float4*)(A + (size_t)(bm + ar) * lda + kt * TBK + ac);
        float4 va1 = *(const float4*)(A + (size_t)(bm + ar) * lda + kt * TBK + ac + 4);
        float4 vb  = *(const float4*)(B + (size_t)br * K + kt * TBK + bc);
        __syncthreads();
        As[ac + 0][ar] = va0.x; As[ac + 1][ar] = va0.y;
        As[ac + 2][ar] = va0.z; As[ac + 3][ar] = va0.w;
        As[ac + 4][ar] = va1.x; As[ac + 5][ar] = va1.y;
        As[ac + 6][ar] = va1.z; As[ac + 7][ar] = va1.w;
        Bs[bc + 0][br] = vb.x; Bs[bc + 1][br] = vb.y;
        Bs[bc + 2][br] = vb.z; Bs[bc + 3][br] = vb.w;
        __syncthreads();
#pragma unroll
        for (int k = 0; k < TBK; ++k) {
            float bv = Bs[k][lane];
#pragma unroll
            for (int i = 0; i < 8; ++i)
                acc[i] = __fmaf_rn(As[k][wrow + i], bv, acc[i]);
        }
    }

#pragma unroll
    for (int i = 0; i < 8; ++i)
        C[(size_t)(bm + wrow + i) * RR + lane] = acc[i];
}

// ---------------------------------------------------------------------------
// Launch
// ---------------------------------------------------------------------------
extern "C" void kernel_launch(void* const* d_in, const int* in_sizes, int n_in,
                              void* d_out, int out_size)
{
    const float* x   = (const float*)d_in[0];
    const float* W1  = (const float*)d_in[1];
    const float* ld1 = (const float*)d_in[2];
    const float* lu1 = (const float*)d_in[3];
    const float* W2  = (const float*)d_in[4];
    const float* ld2 = (const float*)d_in[5];
    const float* lu2 = (const float*)d_in[6];
    float* out = (float*)d_out;

    int8_t *qx, *qw1, *qw2, *qg;
    float *sxT, *sw1T, *sw2T, *sgT, *H, *G, *T1, *T2;
    cudaGetSymbolAddress((void**)&qx,  g_qx);
    cudaGetSymbolAddress((void**)&qw1, g_qw1);
    cudaGetSymbolAddress((void**)&qw2, g_qw2);
    cudaGetSymbolAddress((void**)&qg,  g_qg);
    cudaGetSymbolAddress((void**)&sxT,  g_sxT);
    cudaGetSymbolAddress((void**)&sw1T, g_sw1T);
    cudaGetSymbolAddress((void**)&sw2T, g_sw2T);
    cudaGetSymbolAddress((void**)&sgT,  g_sgT);
    cudaGetSymbolAddress((void**)&H,  g_H);
    cudaGetSymbolAddress((void**)&G,  g_G);
    cudaGetSymbolAddress((void**)&T1, g_T1);
    cudaGetSymbolAddress((void**)&T2, g_T2);

    const int IMMA_SMEM = 2 * STAGES * TILEB + STAGES * 256 * 4 * 2
                        + 2 * 128 * LSTRIDE * 4;          // 153600
    static int smem_set = 0;
    if (!smem_set) {
        cudaFuncSetAttribute(imma_gemm, cudaFuncAttributeMaxDynamicSharedMemorySize,
                             IMMA_SMEM);
        smem_set = 1;
    }

    // 1. fake-quant -> int8 codes + scales
    {
        int tg = MM * G1;
        quant_groups_i8<<<(tg * 32 + 255) / 256, 256>>>(x, qx, sxT, G1, DD, MM, tg);
    }
    {
        int tg = NN1 * G1;
        quant_groups_i8<<<(tg * 32 + 255) / 256, 256>>>(W1, qw1, sw1T, G1, DD, NN1, tg);
    }
    {
        int tg = DD * G2;
        quant_groups_i8<<<(tg * 32 + 255) / 256, 256>>>(W2, qw2, sw2T, G2, INNER, DD, tg);
    }

    // 2. t1 = x @ ld1^T
    gemm_tall<<<MM / TBM, 256>>>(x, DD, ld1, T1, DD);

    // 3. h = fq(x) @ fq(W1)^T + t1 @ lu1^T   (fused IMMA)
    {
        dim3 grid(NN1 / 128, MM / 128);
        imma_gemm<<<grid, 256, IMMA_SMEM>>>(qx, sxT, qw1, sw1T, T1, lu1, H, MM, NN1, DD);
    }

    // 4. g = a * gelu(gate); int8 requant
    {
        int tg = MM * G2;
        gelu_quant_i8<<<(tg * 32 + 255) / 256, 256>>>(H, G, qg, sgT, tg);
    }

    // 5. t2 = g @ ld2^T
    gemm_tall<<<MM / TBM, 256>>>(G, INNER, ld2, T2, INNER);

    // 6. out = fq(g) @ fq(W2)^T + t2 @ lu2^T  (fused IMMA)
    {
        dim3 grid(DD / 128, MM / 128);
        imma_gemm<<<grid, 256, IMMA_SMEM>>>(qg, sgT, qw2, sw2T, T2, lu2, out, MM, DD, INNER);
    }
}

// round 17
// speedup vs baseline: 1.8121x; 1.8121x over previous
#include <cuda_runtime.h>
#include <cuda_bf16.h>
#include <cstddef>
#include <cstdint>
#include <math.h>

#define MM      16384
#define DD      1280
#define INNER   5120
#define NN1     10240
#define RR      32
#define G1      (DD / 64)
#define G2      (INNER / 64)

// ---------------------------------------------------------------------------
// Scratch
// ---------------------------------------------------------------------------
__device__ __nv_bfloat16 g_qx [(size_t)MM * DD];
__device__ __nv_bfloat16 g_qw1[(size_t)NN1 * DD];
__device__ __nv_bfloat16 g_qw2[(size_t)DD * INNER];
__device__ __nv_bfloat16 g_qg [(size_t)MM * INNER];
__device__ float  g_sxT [(size_t)G1 * MM];
__device__ float  g_sw1T[(size_t)G1 * NN1];
__device__ float  g_sw2T[(size_t)G2 * DD];
__device__ float  g_sgT [(size_t)G2 * MM];
__device__ float  g_H [(size_t)MM * NN1];
__device__ float  g_G [(size_t)MM * INNER];
__device__ float  g_T1[(size_t)MM * RR];
__device__ float  g_T2[(size_t)MM * RR];

__device__ __forceinline__ float warp_max_f(float v) {
#pragma unroll
    for (int o = 16; o > 0; o >>= 1)
        v = fmaxf(v, __shfl_xor_sync(0xffffffffu, v, o));
    return v;
}
__device__ __forceinline__ float div_rcp(float x, float y) {
    return __fmul_rn(x, __frcp_rn(y));
}

// ---------------------------------------------------------------------------
// fake_quant (rcp arithmetic) -> bf16 codes (exact: -8..7) + transposed scales
// ---------------------------------------------------------------------------
__global__ void quant_groups_bf16(const float* __restrict__ src,
                                  __nv_bfloat16* __restrict__ q, float* __restrict__ sT,
                                  int gpr, int K, int rows, int total_groups)
{
    int wid = (blockIdx.x * blockDim.x + threadIdx.x) >> 5;
    if (wid >= total_groups) return;
    int lane = threadIdx.x & 31;
    int row  = wid / gpr;
    int g    = wid - row * gpr;
    int col0 = g * 64;
    const float* s = src + (size_t)row * K + col0;
    float v0 = s[lane], v1 = s[lane + 32];
    float m = warp_max_f(fmaxf(fabsf(v0), fabsf(v1)));
    float scale = fmaxf(div_rcp(m, 7.0f), 1e-8f);
    float rs = __frcp_rn(scale);
    float q0 = fminf(fmaxf(rintf(__fmul_rn(v0, rs)), -8.0f), 7.0f);
    float q1 = fminf(fmaxf(rintf(__fmul_rn(v1, rs)), -8.0f), 7.0f);
    __nv_bfloat16* d = q + (size_t)row * K + col0;
    d[lane]      = __float2bfloat16_rn(q0);
    d[lane + 32] = __float2bfloat16_rn(q1);
    if (lane == 0) sT[(size_t)g * rows + row] = scale;
}

// ---------------------------------------------------------------------------
// GEGLU (erff, rcp) + requant of g -> bf16 codes + scales; raw g kept for t2.
// ---------------------------------------------------------------------------
__global__ void gelu_quant_bf16(const float* __restrict__ H, float* __restrict__ G,
                                __nv_bfloat16* __restrict__ qg, float* __restrict__ sgT,
                                int total_groups)
{
    int wid = (blockIdx.x * blockDim.x + threadIdx.x) >> 5;
    if (wid >= total_groups) return;
    int lane = threadIdx.x & 31;
    int row  = wid / G2;
    int g    = wid - row * G2;
    int col0 = g * 64;
    const float* h = H + (size_t)row * NN1 + col0;

    const float SQRT2 = 1.41421356237309504880f;
    float a0 = h[lane],      x0 = h[lane + INNER];
    float a1 = h[lane + 32], x1 = h[lane + 32 + INNER];
    float e0 = erff(div_rcp(x0, SQRT2));
    float e1 = erff(div_rcp(x1, SQRT2));
    float g0 = __fmul_rn(a0, __fmul_rn(__fmul_rn(0.5f, x0), __fadd_rn(e0, 1.0f)));
    float g1 = __fmul_rn(a1, __fmul_rn(__fmul_rn(0.5f, x1), __fadd_rn(e1, 1.0f)));

    float* gp = G + (size_t)row * INNER + col0;
    gp[lane]      = g0;
    gp[lane + 32] = g1;

    float m = warp_max_f(fmaxf(fabsf(g0), fabsf(g1)));
    float scale = fmaxf(div_rcp(m, 7.0f), 1e-8f);
    float rs = __frcp_rn(scale);
    float q0 = fminf(fmaxf(rintf(__fmul_rn(g0, rs)), -8.0f), 7.0f);
    float q1 = fminf(fmaxf(rintf(__fmul_rn(g1, rs)), -8.0f), 7.0f);
    __nv_bfloat16* d = qg + (size_t)row * INNER + col0;
    d[lane]      = __float2bfloat16_rn(q0);
    d[lane + 32] = __float2bfloat16_rn(q1);
    if (lane == 0) sgT[(size_t)g * MM + row] = scale;
}

// ---------------------------------------------------------------------------
// Pipelined group-scaled bf16 HMMA GEMM (NT):
//   C[m,n] = sum_g sA[g][m]*sB[g][n]*Dg(m,n)
// Dg computed with mma.sync.m16n8k16.bf16 into f32 accumulators: products and
// group dots (<=3584) exact integers => identical to the int32 path; fp32
// scale merge in ascending-g order (bit-identical to R13/R14 results).
// 128x128 tile, 8 warps (2x4), warp tile 64x32, 3-stage cp.async pipeline,
// chunk = one 64-element group = 128 bytes/row of bf16.
// ---------------------------------------------------------------------------
#define STAGES  3
#define ASTRIDE 144
#define TILEB   (128 * ASTRIDE)

#define CP16(d, s) asm volatile("cp.async.cg.shared.global [%0], [%1], 16;\n" :: "r"(d), "l"(s))
#define CP4(d, s)  asm volatile("cp.async.ca.shared.global [%0], [%1], 4;\n"  :: "r"(d), "l"(s))
#define CP_COMMIT  asm volatile("cp.async.commit_group;\n")

__global__ void __launch_bounds__(256, 1)
hmma_gemm(const __nv_bfloat16* __restrict__ qA, const float* __restrict__ sAT,
          const __nv_bfloat16* __restrict__ qB, const float* __restrict__ sBT,
          float* __restrict__ C, int M, int N, int K)
{
    extern __shared__ char dsm[];
    char*  smA = dsm;                                    // STAGES*TILEB
    char*  smB = dsm + STAGES * TILEB;                   // STAGES*TILEB
    float* ss  = (float*)(dsm + 2 * STAGES * TILEB);     // STAGES*(128 sa + 128 sb)

    const int tid  = threadIdx.x;
    const int lane = tid & 31;
    const int wid  = tid >> 5;
    const int wm   = (wid >> 2) * 64;
    const int wn   = (wid & 3) * 32;
    const int bm   = blockIdx.y * 128;
    const int bn   = blockIdx.x * 128;
    const int nG   = K >> 6;           // one chunk per 64-elem group

    const uint32_t smA_u = (uint32_t)__cvta_generic_to_shared(smA);
    const uint32_t smB_u = (uint32_t)__cvta_generic_to_shared(smB);
    const uint32_t ss_u  = (uint32_t)__cvta_generic_to_shared(ss);

    const int lr0  = tid >> 3;          // 0..31, +32 per pass
    const int lseg = tid & 7;           // 8 x 16B = 128B row

    float facc[16][4];
#pragma unroll
    for (int i = 0; i < 16; ++i)
#pragma unroll
        for (int j = 0; j < 4; ++j) facc[i][j] = 0.0f;

    // ldmatrix per-lane addressing (b16 fragments)
    const int a_r  = lane & 15;
    const int a_cb = (lane & 16) ? 16 : 0;
    const int b_r  = lane & 7;
    const int b_cb = (lane & 8) ? 16 : 0;

    const int sg2 = tid >> 7;           // 0: sa, 1: sb loader half
    const int sr  = tid & 127;

    auto load_stage = [&](int g, int slot) {
        const __nv_bfloat16* gA = qA + (size_t)bm * K + (size_t)g * 64;
        const __nv_bfloat16* gB = qB + (size_t)bn * K + (size_t)g * 64;
        uint32_t aB = smA_u + slot * TILEB;
        uint32_t bB = smB_u + slot * TILEB;
#pragma unroll
        for (int t = 0; t < 4; ++t) {
            int r = lr0 + t * 32;
            CP16(aB + r * ASTRIDE + lseg * 16,
                 (const char*)(gA + (size_t)r * K) + lseg * 16);
        }
#pragma unroll
        for (int t = 0; t < 4; ++t) {
            int r = lr0 + t * 32;
            CP16(bB + r * ASTRIDE + lseg * 16,
                 (const char*)(gB + (size_t)r * K) + lseg * 16);
        }
        if (sg2 == 0) CP4(ss_u + (slot * 256 + sr) * 4,
                          sAT + (size_t)g * M + bm + sr);
        else          CP4(ss_u + (slot * 256 + 128 + sr) * 4,
                          sBT + (size_t)g * N + bn + sr);
        CP_COMMIT;
    };

#pragma unroll
    for (int s = 0; s < STAGES - 1; ++s)
        load_stage(s, s);

    const int r0 = lane >> 2;
    const int c0 = (lane & 3) * 2;

    for (int g = 0; g < nG; ++g) {
        if (g + STAGES - 1 < nG)
            load_stage(g + STAGES - 1, (g + STAGES - 1) % STAGES);
        asm volatile("cp.async.wait_group %0;\n" :: "n"(STAGES - 1));
        __syncthreads();

        const int slot = g % STAGES;
        const uint32_t aB = smA_u + slot * TILEB;
        const uint32_t bB = smB_u + slot * TILEB;
        const float* sav = ss + slot * 256;
        const float* sbv = sav + 128;

        float cacc[16][4];
#pragma unroll
        for (int i = 0; i < 16; ++i)
#pragma unroll
            for (int j = 0; j < 4; ++j) cacc[i][j] = 0.0f;

#pragma unroll
        for (int kk = 0; kk < 4; ++kk) {       // 4 k16 steps per 64-elem group
            uint32_t af[4][4], bf[4][2];
#pragma unroll
            for (int mi = 0; mi < 4; ++mi) {
                uint32_t addr = aB + (wm + mi * 16 + a_r) * ASTRIDE + kk * 32 + a_cb;
                asm volatile(
                    "ldmatrix.sync.aligned.m8n8.x4.shared.b16 {%0,%1,%2,%3}, [%4];"
                    : "=r"(af[mi][0]), "=r"(af[mi][1]), "=r"(af[mi][2]), "=r"(af[mi][3])
                    : "r"(addr));
            }
#pragma unroll
            for (int ni = 0; ni < 4; ++ni) {
                uint32_t addr = bB + (wn + ni * 8 + b_r) * ASTRIDE + kk * 32 + b_cb;
                asm volatile(
                    "ldmatrix.sync.aligned.m8n8.x2.shared.b16 {%0,%1}, [%2];"
                    : "=r"(bf[ni][0]), "=r"(bf[ni][1])
                    : "r"(addr));
            }
#pragma unroll
            for (int mi = 0; mi < 4; ++mi)
#pragma unroll
                for (int ni = 0; ni < 4; ++ni) {
                    int idx = mi * 4 + ni;
                    asm volatile(
                        "mma.sync.aligned.m16n8k16.row.col.f32.bf16.bf16.f32 "
                        "{%0,%1,%2,%3}, {%4,%5,%6,%7}, {%8,%9}, {%0,%1,%2,%3};"
                        : "+f"(cacc[idx][0]), "+f"(cacc[idx][1]),
                          "+f"(cacc[idx][2]), "+f"(cacc[idx][3])
                        : "r"(af[mi][0]), "r"(af[mi][1]), "r"(af[mi][2]), "r"(af[mi][3]),
                          "r"(bf[ni][0]), "r"(bf[ni][1]));
                }
        }

        // per-group scale merge (ascending g; same ops as R13/R14)
#pragma unroll
        for (int mi = 0; mi < 4; ++mi) {
            float sa0 = sav[wm + mi * 16 + r0];
            float sa1 = sav[wm + mi * 16 + r0 + 8];
#pragma unroll
            for (int ni = 0; ni < 4; ++ni) {
                float sb0 = sbv[wn + ni * 8 + c0];
                float sb1 = sbv[wn + ni * 8 + c0 + 1];
                int idx = mi * 4 + ni;
                facc[idx][0] = __fmaf_rn(__fmul_rn(sa0, sb0), cacc[idx][0], facc[idx][0]);
                facc[idx][1] = __fmaf_rn(__fmul_rn(sa0, sb1), cacc[idx][1], facc[idx][1]);
                facc[idx][2] = __fmaf_rn(__fmul_rn(sa1, sb0), cacc[idx][2], facc[idx][2]);
                facc[idx][3] = __fmaf_rn(__fmul_rn(sa1, sb1), cacc[idx][3], facc[idx][3]);
            }
        }
        __syncthreads();
    }

#pragma unroll
    for (int mi = 0; mi < 4; ++mi)
#pragma unroll
        for (int ni = 0; ni < 4; ++ni) {
            int idx = mi * 4 + ni;
            int row = bm + wm + mi * 16 + r0;
            int col = bn + wn + ni * 8 + c0;
            *(float2*)&C[(size_t)row * N + col] =
                make_float2(facc[idx][0], facc[idx][1]);
            *(float2*)&C[(size_t)(row + 8) * N + col] =
                make_float2(facc[idx][2], facc[idx][3]);
        }
}

// ---------------------------------------------------------------------------
// Skinny tall GEMM: C[M,32] = A[M,K] @ B[32,K]^T (ascending-k FMA chain).
// ---------------------------------------------------------------------------
#define TBM 64
#define TBK 32

__global__ void __launch_bounds__(256, 2)
gemm_tall(const float* __restrict__ A, int lda,
          const float* __restrict__ B,
          float* __restrict__ C, int K)
{
    __shared__ float As[TBK][TBM + 4];
    __shared__ float Bs[TBK][RR];

    const int tid  = threadIdx.x;
    const int lane = tid & 31;
    const int wrow = (tid >> 5) * 8;
    const int bm   = blockIdx.x * TBM;

    float acc[8];
#pragma unroll
    for (int i = 0; i < 8; ++i) acc[i] = 0.0f;

    const int ar = tid >> 2;
    const int ac = (tid & 3) * 8;
    const int br = tid >> 3;
    const int bc = (tid & 7) * 4;

    for (int kt = 0; kt < K / TBK; ++kt) {
        float4 va0 = *(const float4*)(A + (size_t)(bm + ar) * lda + kt * TBK + ac);
        float4 va1 = *(const float4*)(A + (size_t)(bm + ar) * lda + kt * TBK + ac + 4);
        float4 vb  = *(const float4*)(B + (size_t)br * K + kt * TBK + bc);
        __syncthreads();
        As[ac + 0][ar] = va0.x; As[ac + 1][ar] = va0.y;
        As[ac + 2][ar] = va0.z; As[ac + 3][ar] = va0.w;
        As[ac + 4][ar] = va1.x; As[ac + 5][ar] = va1.y;
        As[ac + 6][ar] = va1.z; As[ac + 7][ar] = va1.w;
        Bs[bc + 0][br] = vb.x; Bs[bc + 1][br] = vb.y;
        Bs[bc + 2][br] = vb.z; Bs[bc + 3][br] = vb.w;
        __syncthreads();
#pragma unroll
        for (int k = 0; k < TBK; ++k) {
            float bv = Bs[k][lane];
#pragma unroll
            for (int i = 0; i < 8; ++i)
                acc[i] = __fmaf_rn(As[k][wrow + i], bv, acc[i]);
        }
    }

#pragma unroll
    for (int i = 0; i < 8; ++i)
        C[(size_t)(bm + wrow + i) * RR + lane] = acc[i];
}

// ---------------------------------------------------------------------------
// fp32 GEMM (NT), ascending-k FMA chain, addend D (may alias C) — LoRA adds.
// ---------------------------------------------------------------------------
#define BM 128
#define BN 128
#define BK 16

__global__ void __launch_bounds__(256, 2)
gemm_nt(const float* __restrict__ A, int lda,
        const float* __restrict__ B, int ldb,
        float* __restrict__ C, int ldc,
        const float* __restrict__ D,
        int M, int N, int K)
{
    __shared__ float As[2][BK][BM];
    __shared__ float Bs[2][BK][BN];

    const int tid = threadIdx.x;
    const int bm = blockIdx.y * BM;
    const int bn = blockIdx.x * BN;

    const int lr = tid >> 2;
    const int lk = (tid & 3) << 2;

    const int tm0 = (tid >> 4) << 3;
    const int tn0 = (tid & 15) << 3;

    const float* Arow0 = A + (size_t)(bm + lr) * lda + lk;
    const float* Arow1 = A + (size_t)(bm + lr + 64) * lda + lk;
    const int nb0 = bn + lr, nb1 = bn + lr + 64;
    const float* Brow0 = B + (size_t)nb0 * ldb + lk;
    const float* Brow1 = B + (size_t)nb1 * ldb + lk;
    const bool bv0 = nb0 < N, bv1 = nb1 < N;

    float acc[8][8];
#pragma unroll
    for (int i = 0; i < 8; ++i)
#pragma unroll
        for (int j = 0; j < 8; ++j) acc[i][j] = 0.0f;

    const int T = K / BK;
    const float4 z4 = make_float4(0.f, 0.f, 0.f, 0.f);
    float4 ra0, ra1, rb0, rb1;

    ra0 = *(const float4*)(Arow0);
    ra1 = *(const float4*)(Arow1);
    rb0 = bv0 ? *(const float4*)(Brow0) : z4;
    rb1 = bv1 ? *(const float4*)(Brow1) : z4;

    As[0][lk + 0][lr] = ra0.x; As[0][lk + 1][lr] = ra0.y;
    As[0][lk + 2][lr] = ra0.z; As[0][lk + 3][lr] = ra0.w;
    As[0][lk + 0][lr + 64] = ra1.x; As[0][lk + 1][lr + 64] = ra1.y;
    As[0][lk + 2][lr + 64] = ra1.z; As[0][lk + 3][lr + 64] = ra1.w;
    Bs[0][lk + 0][lr] = rb0.x; Bs[0][lk + 1][lr] = rb0.y;
    Bs[0][lk + 2][lr] = rb0.z; Bs[0][lk + 3][lr] = rb0.w;
    Bs[0][lk + 0][lr + 64] = rb1.x; Bs[0][lk + 1][lr + 64] = rb1.y;
    Bs[0][lk + 2][lr + 64] = rb1.z; Bs[0][lk + 3][lr + 64] = rb1.w;
    __syncthreads();

    for (int t = 0; t < T; ++t) {
        const int cur = t & 1;
        if (t + 1 < T) {
            const int ko = (t + 1) * BK;
            ra0 = *(const float4*)(Arow0 + ko);
            ra1 = *(const float4*)(Arow1 + ko);
            rb0 = bv0 ? *(const float4*)(Brow0 + ko) : z4;
            rb1 = bv1 ? *(const float4*)(Brow1 + ko) : z4;
        }
#pragma unroll
        for (int k = 0; k < BK; ++k) {
            float a[8], b[8];
            *(float4*)(a)     = *(const float4*)&As[cur][k][tm0];
            *(float4*)(a + 4) = *(const float4*)&As[cur][k][tm0 + 4];
            *(float4*)(b)     = *(const float4*)&Bs[cur][k][tn0];
            *(float4*)(b + 4) = *(const float4*)&Bs[cur][k][tn0 + 4];
#pragma unroll
            for (int i = 0; i < 8; ++i)
#pragma unroll
                for (int j = 0; j < 8; ++j)
                    acc[i][j] = __fmaf_rn(a[i], b[j], acc[i][j]);
        }
        if (t + 1 < T) {
            const int nxt = cur ^ 1;
            As[nxt][lk + 0][lr] = ra0.x; As[nxt][lk + 1][lr] = ra0.y;
            As[nxt][lk + 2][lr] = ra0.z; As[nxt][lk + 3][lr] = ra0.w;
            As[nxt][lk + 0][lr + 64] = ra1.x; As[nxt][lk + 1][lr + 64] = ra1.y;
            As[nxt][lk + 2][lr + 64] = ra1.z; As[nxt][lk + 3][lr + 64] = ra1.w;
            Bs[nxt][lk + 0][lr] = rb0.x; Bs[nxt][lk + 1][lr] = rb0.y;
            Bs[nxt][lk + 2][lr] = rb0.z; Bs[nxt][lk + 3][lr] = rb0.w;
            Bs[nxt][lk + 0][lr + 64] = rb1.x; Bs[nxt][lk + 1][lr + 64] = rb1.y;
            Bs[nxt][lk + 2][lr + 64] = rb1.z; Bs[nxt][lk + 3][lr + 64] = rb1.w;
            __syncthreads();
        }
    }

#pragma unroll
    for (int i = 0; i < 8; ++i) {
        const size_t roff = (size_t)(bm + tm0 + i) * ldc + bn + tn0;
        float* Crow = C + roff;
        float v[8];
#pragma unroll
        for (int j = 0; j < 8; ++j) v[j] = acc[i][j];
        if (D) {
            const float* Drow = D + roff;
#pragma unroll
            for (int j = 0; j < 8; ++j)
                if (bn + tn0 + j < N) v[j] = __fadd_rn(v[j], Drow[j]);
        }
        if (bn + tn0 + 8 <= N) {
            *(float4*)(Crow)     = make_float4(v[0], v[1], v[2], v[3]);
            *(float4*)(Crow + 4) = make_float4(v[4], v[5], v[6], v[7]);
        } else {
#pragma unroll
            for (int j = 0; j < 8; ++j)
                if (bn + tn0 + j < N) Crow[j] = v[j];
        }
    }
}

// ---------------------------------------------------------------------------
// Launch
// ---------------------------------------------------------------------------
extern "C" void kernel_launch(void* const* d_in, const int* in_sizes, int n_in,
                              void* d_out, int out_size)
{
    const float* x   = (const float*)d_in[0];
    const float* W1  = (const float*)d_in[1];
    const float* ld1 = (const float*)d_in[2];
    const float* lu1 = (const float*)d_in[3];
    const float* W2  = (const float*)d_in[4];
    const float* ld2 = (const float*)d_in[5];
    const float* lu2 = (const float*)d_in[6];
    float* out = (float*)d_out;

    __nv_bfloat16 *qx, *qw1, *qw2, *qg;
    float *sxT, *sw1T, *sw2T, *sgT, *H, *G, *T1, *T2;
    cudaGetSymbolAddress((void**)&qx,  g_qx);
    cudaGetSymbolAddress((void**)&qw1, g_qw1);
    cudaGetSymbolAddress((void**)&qw2, g_qw2);
    cudaGetSymbolAddress((void**)&qg,  g_qg);
    cudaGetSymbolAddress((void**)&sxT,  g_sxT);
    cudaGetSymbolAddress((void**)&sw1T, g_sw1T);
    cudaGetSymbolAddress((void**)&sw2T, g_sw2T);
    cudaGetSymbolAddress((void**)&sgT,  g_sgT);
    cudaGetSymbolAddress((void**)&H,  g_H);
    cudaGetSymbolAddress((void**)&G,  g_G);
    cudaGetSymbolAddress((void**)&T1, g_T1);
    cudaGetSymbolAddress((void**)&T2, g_T2);

    const int HM_SMEM = 2 * STAGES * TILEB + STAGES * 256 * 4;   // 113664
    static int smem_set = 0;
    if (!smem_set) {
        cudaFuncSetAttribute(hmma_gemm, cudaFuncAttributeMaxDynamicSharedMemorySize,
                             HM_SMEM);
        smem_set = 1;
    }

    // 1. fake-quant -> bf16 codes + scales
    {
        int tg = MM * G1;
        quant_groups_bf16<<<(tg * 32 + 255) / 256, 256>>>(x, qx, sxT, G1, DD, MM, tg);
    }
    {
        int tg = NN1 * G1;
        quant_groups_bf16<<<(tg * 32 + 255) / 256, 256>>>(W1, qw1, sw1T, G1, DD, NN1, tg);
    }
    {
        int tg = DD * G2;
        quant_groups_bf16<<<(tg * 32 + 255) / 256, 256>>>(W2, qw2, sw2T, G2, INNER, DD, tg);
    }

    // 2. t1 = x @ ld1^T
    gemm_tall<<<MM / TBM, 256>>>(x, DD, ld1, T1, DD);

    // 3. main1 = fq(x) @ fq(W1)^T  (bf16 HMMA, exact group dots)
    {
        dim3 grid(NN1 / 128, MM / 128);
        hmma_gemm<<<grid, 256, HM_SMEM>>>(qx, sxT, qw1, sw1T, H, MM, NN1, DD);
    }

    // 4. h = (t1 @ lu1^T) + main1
    {
        dim3 grid(NN1 / BN, MM / BM);
        gemm_nt<<<grid, 256>>>(T1, RR, lu1, RR, H, NN1, H, MM, NN1, RR);
    }

    // 5. g = a * gelu(gate); bf16 requant
    {
        int tg = MM * G2;
        gelu_quant_bf16<<<(tg * 32 + 255) / 256, 256>>>(H, G, qg, sgT, tg);
    }

    // 6. t2 = g @ ld2^T
    gemm_tall<<<MM / TBM, 256>>>(G, INNER, ld2, T2, INNER);

    // 7. main2 = fq(g) @ fq(W2)^T -> out  (bf16 HMMA)
    {
        dim3 grid(DD / 128, MM / 128);
        hmma_gemm<<<grid, 256, HM_SMEM>>>(qg, sgT, qw2, sw2T, out, MM, DD, INNER);
    }

    // 8. out = (t2 @ lu2^T) + main2
    {
        dim3 grid(DD / BN, MM / BM);
        gemm_nt<<<grid, 256>>>(T2, RR, lu2, RR, out, DD, out, MM, DD, RR);
    }
}